// round 5
// baseline (speedup 1.0000x reference)
#include <cuda_runtime.h>
#include <cstdint>
#include <cstddef>

typedef unsigned long long ull;
#define DINLINE __device__ __forceinline__

namespace {
constexpr int Tlen = 512, OUTW = 24;
constexpr int CL = 8;        // CTAs per cluster (column split)
constexpr int Br = 16;       // batch rows per cluster
constexpr int NTHR = 256;    // 8 warps

constexpr int H1S = 258;     // padded strides
constexpr int H2S = 130;
constexpr int XSS = 68;

constexpr int OFF_R1 = 0;                    // [256][96]
constexpr int OFF_K1 = OFF_R1 + 256 * 96;    // [64][96]
constexpr int OFF_K2 = OFF_K1 + 64 * 96;     // [256][48]
constexpr int OFF_R2 = OFF_K2 + 256 * 48;    // [128][48]
constexpr int OFF_H1 = OFF_R2 + 128 * 48;    // [16][258]
constexpr int OFF_H2 = OFF_H1 + Br * H1S;    // [16][130]
constexpr int OFF_XS = OFF_H2 + Br * H2S;    // [16][68]
constexpr int OFF_SC = OFF_XS + Br * XSS;    // scratch 1632 floats (816 ull)
constexpr int SMEM_FLOATS = OFF_SC + 1632;   // 58080
constexpr size_t SMEM_BYTES = SMEM_FLOATS * sizeof(float);  // 232320
}  // namespace

DINLINE float sigf(float v) { return __fdividef(1.0f, 1.0f + __expf(-v)); }
DINLINE float tanh_fast(float v) {
    float e = __expf(2.0f * fabsf(v));
    float t = 1.0f - __fdividef(2.0f, e + 1.0f);
    return copysignf(t, v);
}
DINLINE void cl_arrive() { asm volatile("barrier.cluster.arrive.aligned;" ::: "memory"); }
DINLINE void cl_wait()   { asm volatile("barrier.cluster.wait.aligned;"   ::: "memory"); }
DINLINE uint32_t mapa_u32(uint32_t addr, uint32_t rank) {
    uint32_t p;
    asm("mapa.shared::cluster.u32 %0, %1, %2;" : "=r"(p) : "r"(addr), "r"(rank));
    return p;
}
DINLINE void st_rem64(uint32_t addr, ull v) {
    asm volatile("st.shared::cluster.b64 [%0], %1;" :: "r"(addr), "l"(v) : "memory");
}
DINLINE ull pk2(float a, float b) {
    ull r; asm("mov.b64 %0, {%1, %2};" : "=l"(r) : "f"(a), "f"(b)); return r;
}
DINLINE float2 upk(ull v) {
    float2 r; asm("mov.b64 {%0, %1}, %2;" : "=f"(r.x), "=f"(r.y) : "l"(v)); return r;
}
DINLINE void f2(ull& d, ull a, ull b) {
    asm("fma.rn.f32x2 %0, %1, %2, %0;" : "+l"(d) : "l"(a), "l"(b));
}
DINLINE void a2(ull& d, ull b) {
    asm("add.rn.f32x2 %0, %0, %1;" : "+l"(d) : "l"(b));
}

__global__ void __launch_bounds__(NTHR, 1) __cluster_dims__(CL, 1, 1)
gru_stack_kernel(const float* __restrict__ x,  const float* __restrict__ k1,
                 const float* __restrict__ r1, const float* __restrict__ b1,
                 const float* __restrict__ k2, const float* __restrict__ r2,
                 const float* __restrict__ b2, const float* __restrict__ w3,
                 const float* __restrict__ b3, const float* __restrict__ w4,
                 const float* __restrict__ b4, const float* __restrict__ w5,
                 const float* __restrict__ b5, float* __restrict__ out)
{
    extern __shared__ float sm[];
    const int tid = threadIdx.x;
    const int c = blockIdx.x & (CL - 1);
    const int g = blockIdx.x >> 3;

    // ---- Stage weight slices (col j = gate*Ulocal + local_unit) ----
    for (int idx = tid; idx < 256 * 96; idx += NTHR) {
        int k = idx / 96, j = idx % 96;
        sm[OFF_R1 + idx] = r1[k * 768 + (j >> 5) * 256 + (c << 5) + (j & 31)];
    }
    for (int idx = tid; idx < 64 * 96; idx += NTHR) {
        int k = idx / 96, j = idx % 96;
        sm[OFF_K1 + idx] = k1[k * 768 + (j >> 5) * 256 + (c << 5) + (j & 31)];
    }
    for (int idx = tid; idx < 256 * 48; idx += NTHR) {
        int k = idx / 48, j = idx % 48;
        sm[OFF_K2 + idx] = k2[k * 384 + (j >> 4) * 128 + (c << 4) + (j & 15)];
    }
    for (int idx = tid; idx < 128 * 48; idx += NTHR) {
        int k = idx / 48, j = idx % 48;
        sm[OFF_R2 + idx] = r2[k * 384 + (j >> 4) * 128 + (c << 4) + (j & 15)];
    }
    for (int idx = tid; idx < Br * H1S; idx += NTHR) sm[OFF_H1 + idx] = 0.0f;
    for (int idx = tid; idx < Br * H2S; idx += NTHR) sm[OFF_H2 + idx] = 0.0f;
    {   // x(0)
        int r = tid >> 4, f = (tid & 15) * 4;
        float4 v = *(const float4*)(x + ((size_t)(g * Br + r) * Tlen + 0) * 64 + f);
        *(float4*)(sm + OFF_XS + r * XSS + f) = v;
    }

    // ---- thread mappings ----
    const int kcA = tid >> 7;               // 2-way k-split (GRU1)
    const int rgA = (tid >> 3) & 15;        // 1 row per thread
    const int ctA = tid & 7;                // 4 units
    const int kcB = tid >> 6;               // 4-way k-split (GRU2)
    const int rgB = (tid >> 2) & 15;        // 1 row
    const int ctB = tid & 3;                // 4 units

    // ---- biases in registers ----
    ull bzA[2], brA[2], bxA[2], bhA[2];
    if (kcA == 0) {
        #pragma unroll
        for (int p = 0; p < 2; p++) {
            int u0 = (c << 5) + ctA * 4 + p * 2, u1 = u0 + 1;
            bzA[p] = pk2(b1[u0] + b1[768 + u0],        b1[u1] + b1[768 + u1]);
            brA[p] = pk2(b1[256 + u0] + b1[1024 + u0], b1[256 + u1] + b1[1024 + u1]);
            bxA[p] = pk2(b1[512 + u0],                 b1[512 + u1]);
            bhA[p] = pk2(b1[1280 + u0],                b1[1280 + u1]);
        }
    }
    ull bzB[2], brB[2], bxB[2], bhB[2];
    if (kcB == 0) {
        #pragma unroll
        for (int p = 0; p < 2; p++) {
            int u0 = (c << 4) + ctB * 4 + p * 2, u1 = u0 + 1;
            bzB[p] = pk2(b2[u0] + b2[384 + u0],        b2[u1] + b2[384 + u1]);
            brB[p] = pk2(b2[128 + u0] + b2[512 + u0],  b2[128 + u1] + b2[512 + u1]);
            bxB[p] = pk2(b2[256 + u0],                 b2[256 + u1]);
            bhB[p] = pk2(b2[640 + u0],                 b2[640 + u1]);
        }
    }

    uint32_t smem_base;
    asm("{ .reg .u64 t; cvta.to.shared.u64 t, %1; cvt.u32.u64 %0, t; }"
        : "=r"(smem_base) : "l"(sm));
    const uint32_t h1la = smem_base + (uint32_t)(OFF_H1 + rgA * H1S + (c << 5) + ctA * 4) * 4u;
    const uint32_t h2la = smem_base + (uint32_t)(OFF_H2 + rgB * H2S + (c << 4) + ctB * 4) * 4u;

    const ulonglong2* K1p = (const ulonglong2*)(sm + OFF_K1);
    const ulonglong2* R1p = (const ulonglong2*)(sm + OFF_R1);
    const ulonglong2* K2p = (const ulonglong2*)(sm + OFF_K2);
    const ulonglong2* R2p = (const ulonglong2*)(sm + OFF_R2);
    ull* scU = (ull*)(sm + OFF_SC);

    const int xr_row = tid >> 4, xr_f = (tid & 15) * 4;

    __syncthreads();
    cl_arrive(); cl_wait();

    for (int t = 0; t < Tlen; t++) {
        // prefetch x(t+1) -> registers (stored to smem after sync S1)
        float4 xr;
        if (t + 1 < Tlen)
            xr = *(const float4*)(x + ((size_t)(g * Br + xr_row) * Tlen + (t + 1)) * 64 + xr_f);

        // ================= GRU1 (1 row x 4 units, 2-way k-split) =================
        ull az[2], ar[2], ax[2], ah[2];
        #pragma unroll
        for (int p = 0; p < 2; p++) {
            az[p] = (kcA == 0) ? bzA[p] : 0ull;
            ar[p] = (kcA == 0) ? brA[p] : 0ull;
            ax[p] = (kcA == 0) ? bxA[p] : 0ull;
            ah[p] = (kcA == 0) ? bhA[p] : 0ull;
        }
        const float* hrow1 = sm + OFF_H1 + rgA * H1S;
        if (kcA == 0) {   // input projection (x @ k1), k=0..63
            const float* sx = sm + OFF_XS + rgA * XSS;
            #pragma unroll 4
            for (int k = 0; k < 64; k++) {
                ull v = pk2(sx[k], sx[k]);
                ulonglong2 wz = K1p[k * 24 + ctA];
                ulonglong2 wr = K1p[k * 24 + 8 + ctA];
                ulonglong2 wh = K1p[k * 24 + 16 + ctA];
                f2(az[0], v, wz.x); f2(az[1], v, wz.y);
                f2(ar[0], v, wr.x); f2(ar[1], v, wr.y);
                f2(ax[0], v, wh.x); f2(ax[1], v, wh.y);
            }
        }
        {   // recurrent projection (h1 @ r1): kc0 k 0..95, kc1 k 96..255
            const int kb = kcA ? 96 : 0, ke = kcA ? 256 : 96;
            #pragma unroll 4
            for (int k = kb; k < ke; k++) {
                ull v = pk2(hrow1[k], hrow1[k]);
                ulonglong2 wz = R1p[k * 24 + ctA];
                ulonglong2 wr = R1p[k * 24 + 8 + ctA];
                ulonglong2 wh = R1p[k * 24 + 16 + ctA];
                f2(az[0], v, wz.x); f2(az[1], v, wz.y);
                f2(ar[0], v, wr.x); f2(ar[1], v, wr.y);
                f2(ah[0], v, wh.x); f2(ah[1], v, wh.y);
            }
        }
        cl_arrive();                          // A: done reading h1(t-1)
        if (kcA == 1) {
            #pragma unroll
            for (int p = 0; p < 2; p++) {
                scU[rgA * 50 +      ctA * 2 + p] = az[p];
                scU[rgA * 50 + 16 + ctA * 2 + p] = ar[p];
                scU[rgA * 50 + 32 + ctA * 2 + p] = ah[p];
            }
        }
        __syncthreads();                      // S1
        if (t + 1 < Tlen)
            *(float4*)(sm + OFF_XS + xr_row * XSS + xr_f) = xr;
        float hn1[4];
        if (kcA == 0) {
            #pragma unroll
            for (int p = 0; p < 2; p++) {
                a2(az[p], scU[rgA * 50 +      ctA * 2 + p]);
                a2(ar[p], scU[rgA * 50 + 16 + ctA * 2 + p]);
                a2(ah[p], scU[rgA * 50 + 32 + ctA * 2 + p]);
                float2 vz = upk(az[p]), vr = upk(ar[p]);
                float2 vx = upk(ax[p]), vh = upk(ah[p]);
                int col = (c << 5) + ctA * 4 + p * 2;
                float hp0 = hrow1[col], hp1 = hrow1[col + 1];
                float z0 = sigf(vz.x), r0 = sigf(vr.x);
                float hh0 = tanh_fast(vx.x + r0 * vh.x);
                float z1 = sigf(vz.y), r1g = sigf(vr.y);
                float hh1 = tanh_fast(vx.y + r1g * vh.y);
                hn1[p * 2]     = z0 * hp0 + (1.0f - z0) * hh0;
                hn1[p * 2 + 1] = z1 * hp1 + (1.0f - z1) * hh1;
            }
        }
        cl_wait();                            // A complete
        if (kcA == 0) {                       // replicate h1(t)
            ull q0 = pk2(hn1[0], hn1[1]), q1 = pk2(hn1[2], hn1[3]);
            #pragma unroll
            for (int rk = 0; rk < CL; rk++) {
                uint32_t pa = mapa_u32(h1la, (uint32_t)rk);
                st_rem64(pa, q0); st_rem64(pa + 8, q1);
            }
        }
        cl_arrive();                          // B

        // ===== GRU2 recurrent proj (h2 @ r2) — overlaps barrier B =====
        ull bz[2], br2[2], bx[2], bh[2];
        #pragma unroll
        for (int p = 0; p < 2; p++) {
            bz[p]  = (kcB == 0) ? bzB[p] : 0ull;
            br2[p] = (kcB == 0) ? brB[p] : 0ull;
            bx[p]  = (kcB == 0) ? bxB[p] : 0ull;
            bh[p]  = (kcB == 0) ? bhB[p] : 0ull;
        }
        {
            const float* h2row = sm + OFF_H2 + rgB * H2S;
            const int kb = kcB * 32;
            #pragma unroll 4
            for (int kk = 0; kk < 32; kk++) {
                int k = kb + kk;
                ull v = pk2(h2row[k], h2row[k]);
                ulonglong2 wz = R2p[k * 12 + ctB];
                ulonglong2 wr = R2p[k * 12 + 4 + ctB];
                ulonglong2 wh = R2p[k * 12 + 8 + ctB];
                f2(bz[0], v, wz.x); f2(bz[1], v, wz.y);
                f2(br2[0], v, wr.x); f2(br2[1], v, wr.y);
                f2(bh[0], v, wh.x); f2(bh[1], v, wh.y);
            }
        }
        cl_wait();                            // B complete: h1(t) visible
        {   // GRU2 input proj (h1(t) @ k2)
            const float* h1row = sm + OFF_H1 + rgB * H1S;
            const int kb = kcB * 64;
            #pragma unroll 4
            for (int kk = 0; kk < 64; kk++) {
                int k = kb + kk;
                ull v = pk2(h1row[k], h1row[k]);
                ulonglong2 wz = K2p[k * 12 + ctB];
                ulonglong2 wr = K2p[k * 12 + 4 + ctB];
                ulonglong2 wh = K2p[k * 12 + 8 + ctB];
                f2(bz[0], v, wz.x); f2(bz[1], v, wz.y);
                f2(br2[0], v, wr.x); f2(br2[1], v, wr.y);
                f2(bx[0], v, wh.x); f2(bx[1], v, wh.y);
            }
        }
        cl_arrive();                          // C: done reading h2(t-1)
        if (kcB > 0) {                        // phase 1: z, r
            int m = kcB - 1;
            #pragma unroll
            for (int p = 0; p < 2; p++) {
                scU[m * 272 + rgB * 17 +     ctB * 2 + p] = bz[p];
                scU[m * 272 + rgB * 17 + 8 + ctB * 2 + p] = br2[p];
            }
        }
        __syncthreads();                      // S2
        if (kcB == 0) {
            #pragma unroll
            for (int m = 0; m < 3; m++)
                #pragma unroll
                for (int p = 0; p < 2; p++) {
                    a2(bz[p],  scU[m * 272 + rgB * 17 +     ctB * 2 + p]);
                    a2(br2[p], scU[m * 272 + rgB * 17 + 8 + ctB * 2 + p]);
                }
        }
        __syncthreads();                      // S3
        if (kcB > 0) {                        // phase 2: hx, hh
            int m = kcB - 1;
            #pragma unroll
            for (int p = 0; p < 2; p++) {
                scU[m * 272 + rgB * 17 +     ctB * 2 + p] = bx[p];
                scU[m * 272 + rgB * 17 + 8 + ctB * 2 + p] = bh[p];
            }
        }
        __syncthreads();                      // S4
        float hn2[4];
        if (kcB == 0) {
            #pragma unroll
            for (int p = 0; p < 2; p++) {
                #pragma unroll
                for (int m = 0; m < 3; m++) {
                    a2(bx[p], scU[m * 272 + rgB * 17 +     ctB * 2 + p]);
                    a2(bh[p], scU[m * 272 + rgB * 17 + 8 + ctB * 2 + p]);
                }
                float2 vz = upk(bz[p]), vr = upk(br2[p]);
                float2 vx = upk(bx[p]), vh = upk(bh[p]);
                int col = (c << 4) + ctB * 4 + p * 2;
                float hp0 = sm[OFF_H2 + rgB * H2S + col];
                float hp1 = sm[OFF_H2 + rgB * H2S + col + 1];
                float z0 = sigf(vz.x), r0 = sigf(vr.x);
                float hh0 = tanh_fast(vx.x + r0 * vh.x);
                float z1 = sigf(vz.y), r1g = sigf(vr.y);
                float hh1 = tanh_fast(vx.y + r1g * vh.y);
                hn2[p * 2]     = z0 * hp0 + (1.0f - z0) * hh0;
                hn2[p * 2 + 1] = z1 * hp1 + (1.0f - z1) * hh1;
            }
        }
        __syncthreads();                      // S5: scratch reads done before next step's writes
        cl_wait();                            // C complete
        if (kcB == 0) {                       // replicate h2(t)
            ull q0 = pk2(hn2[0], hn2[1]), q1 = pk2(hn2[2], hn2[3]);
            #pragma unroll
            for (int rk = 0; rk < CL; rk++) {
                uint32_t pa = mapa_u32(h2la, (uint32_t)rk);
                st_rem64(pa, q0); st_rem64(pa + 8, q1);
            }
        }
    }
    cl_arrive(); cl_wait();                   // final h2 visible everywhere

    // ================= Dense head (rank 0) =================
    if (c == 0) {
        float* sD3 = sm + OFF_SC;             // [16][64]
        float* sD4 = sm + OFF_SC + Br * 64;   // [16][32]
        __syncthreads();
        for (int idx = tid; idx < Br * 64; idx += NTHR) {
            int r = idx >> 6, o = idx & 63;
            float a = b3[o];
            #pragma unroll 8
            for (int k = 0; k < 128; k++) a += sm[OFF_H2 + r * H2S + k] * w3[k * 64 + o];
            sD3[idx] = a;
        }
        __syncthreads();
        for (int idx = tid; idx < Br * 32; idx += NTHR) {
            int r = idx >> 5, o = idx & 31;
            float a = b4[o];
            #pragma unroll 8
            for (int k = 0; k < 64; k++) a += sD3[r * 64 + k] * w4[k * 32 + o];
            sD4[idx] = a;
        }
        __syncthreads();
        for (int idx = tid; idx < Br * OUTW; idx += NTHR) {
            int r = idx / OUTW, o = idx % OUTW;
            float a = b5[o];
            #pragma unroll 8
            for (int k = 0; k < 32; k++) a += sD4[r * 32 + k] * w5[k * OUTW + o];
            out[(g * Br + r) * OUTW + o] = a;
        }
    }
}

extern "C" void kernel_launch(void* const* d_in, const int* in_sizes, int n_in,
                              void* d_out, int out_size) {
    (void)in_sizes; (void)n_in; (void)out_size;
    const float* x  = (const float*)d_in[0];
    const float* k1 = (const float*)d_in[1];
    const float* r1 = (const float*)d_in[2];
    const float* b1 = (const float*)d_in[3];
    const float* k2 = (const float*)d_in[4];
    const float* r2 = (const float*)d_in[5];
    const float* b2 = (const float*)d_in[6];
    const float* w3 = (const float*)d_in[7];
    const float* b3 = (const float*)d_in[8];
    const float* w4 = (const float*)d_in[9];
    const float* b4 = (const float*)d_in[10];
    const float* w5 = (const float*)d_in[11];
    const float* b5 = (const float*)d_in[12];
    float* out = (float*)d_out;

    cudaFuncSetAttribute(gru_stack_kernel,
                         cudaFuncAttributeMaxDynamicSharedMemorySize,
                         (int)SMEM_BYTES);
    gru_stack_kernel<<<128, NTHR, SMEM_BYTES>>>(
        x, k1, r1, b1, k2, r2, b2, w3, b3, w4, b4, w5, b5, out);
}

// round 6
// speedup vs baseline: 1.2441x; 1.2441x over previous
#include <cuda_runtime.h>
#include <cstdint>
#include <cstddef>

typedef unsigned long long ull;
#define DINLINE __device__ __forceinline__

namespace {
constexpr int Tlen = 512, OUTW = 24;
constexpr int CL = 8, Br = 16, NTHR = 128;
constexpr int H1S = 258, H2S = 130, XSS = 68;

constexpr int OFF_MB = 0;                    // 3 mbarriers (24B) + pad
constexpr int OFF_R1 = 8;
constexpr int OFF_K1 = OFF_R1 + 256 * 96;
constexpr int OFF_K2 = OFF_K1 + 64 * 96;
constexpr int OFF_R2 = OFF_K2 + 256 * 48;
constexpr int OFF_H1 = OFF_R2 + 128 * 48;
constexpr int OFF_H2 = OFF_H1 + Br * H1S;
constexpr int OFF_XS = OFF_H2 + Br * H2S;
constexpr int OFF_SC = OFF_XS + Br * XSS;    // 816 ull scratch (shared)
constexpr int SMEM_FLOATS = OFF_SC + 1632;   // 58088
constexpr size_t SMEM_BYTES = SMEM_FLOATS * sizeof(float);  // 232352
}

DINLINE float sigf(float v) { return __fdividef(1.0f, 1.0f + __expf(-v)); }
DINLINE float tanh_fast(float v) {
    float e = __expf(2.0f * fabsf(v));
    return copysignf(1.0f - __fdividef(2.0f, e + 1.0f), v);
}
DINLINE void cl_sync() {
    asm volatile("barrier.cluster.arrive.aligned;" ::: "memory");
    asm volatile("barrier.cluster.wait.aligned;" ::: "memory");
}
DINLINE uint32_t mapa_u32(uint32_t a, uint32_t r) {
    uint32_t p; asm("mapa.shared::cluster.u32 %0, %1, %2;" : "=r"(p) : "r"(a), "r"(r));
    return p;
}
DINLINE void st_rem64(uint32_t a, ull v) {
    asm volatile("st.shared::cluster.b64 [%0], %1;" :: "r"(a), "l"(v) : "memory");
}
DINLINE ull pk2(float a, float b) {
    ull r; asm("mov.b64 %0, {%1, %2};" : "=l"(r) : "f"(a), "f"(b)); return r;
}
DINLINE float2 upk(ull v) {
    float2 r; asm("mov.b64 {%0, %1}, %2;" : "=f"(r.x), "=f"(r.y) : "l"(v)); return r;
}
DINLINE void f2(ull& d, ull a, ull b) {
    asm("fma.rn.f32x2 %0, %1, %2, %0;" : "+l"(d) : "l"(a), "l"(b));
}
DINLINE void a2(ull& d, ull b) { asm("add.rn.f32x2 %0, %0, %1;" : "+l"(d) : "l"(b)); }
DINLINE void mb_init(uint32_t a, uint32_t n) {
    asm volatile("mbarrier.init.shared.b64 [%0], %1;" :: "r"(a), "r"(n) : "memory");
}
DINLINE void mb_arrive_rel(uint32_t laddr, uint32_t rank) {
    asm volatile("{ .reg .b32 ra;\n\t"
        "mapa.shared::cluster.u32 ra, %0, %1;\n\t"
        "mbarrier.arrive.release.cluster.shared::cluster.b64 _, [ra]; }"
        :: "r"(laddr), "r"(rank) : "memory");
}
DINLINE void mb_wait(uint32_t a, uint32_t par) {
    asm volatile("{ .reg .pred P;\n"
        "W%=:\n\t"
        "mbarrier.try_wait.parity.acquire.cluster.shared::cta.b64 P, [%0], %1, 0x989680;\n\t"
        "@P bra.uni D%=;\n\t"
        "bra.uni W%=;\n"
        "D%=: }" :: "r"(a), "r"(par) : "memory");
}

__global__ void __launch_bounds__(NTHR, 1) __cluster_dims__(CL, 1, 1)
gru_stack_kernel(const float* __restrict__ x,  const float* __restrict__ k1,
                 const float* __restrict__ r1, const float* __restrict__ b1,
                 const float* __restrict__ k2, const float* __restrict__ r2,
                 const float* __restrict__ b2, const float* __restrict__ w3,
                 const float* __restrict__ b3, const float* __restrict__ w4,
                 const float* __restrict__ b4, const float* __restrict__ w5,
                 const float* __restrict__ b5, float* __restrict__ out)
{
    extern __shared__ float sm[];
    const int tid = threadIdx.x;
    const int c = blockIdx.x & (CL - 1);
    const int g = blockIdx.x >> 3;

    uint32_t smem_base;
    asm("{ .reg .u64 t; cvta.to.shared.u64 t, %1; cvt.u32.u64 %0, t; }"
        : "=r"(smem_base) : "l"(sm));
    const uint32_t mbFREE = smem_base, mbRDY1 = smem_base + 8, mbRDY2 = smem_base + 16;
    if (tid == 0) { mb_init(mbFREE, 8); mb_init(mbRDY1, 8); mb_init(mbRDY2, 8); }

    for (int idx = tid; idx < 256 * 96; idx += NTHR) {
        int k = idx / 96, j = idx % 96;
        sm[OFF_R1 + idx] = r1[k * 768 + (j >> 5) * 256 + (c << 5) + (j & 31)];
    }
    for (int idx = tid; idx < 64 * 96; idx += NTHR) {
        int k = idx / 96, j = idx % 96;
        sm[OFF_K1 + idx] = k1[k * 768 + (j >> 5) * 256 + (c << 5) + (j & 31)];
    }
    for (int idx = tid; idx < 256 * 48; idx += NTHR) {
        int k = idx / 48, j = idx % 48;
        sm[OFF_K2 + idx] = k2[k * 384 + (j >> 4) * 128 + (c << 4) + (j & 15)];
    }
    for (int idx = tid; idx < 128 * 48; idx += NTHR) {
        int k = idx / 48, j = idx % 48;
        sm[OFF_R2 + idx] = r2[k * 384 + (j >> 4) * 128 + (c << 4) + (j & 15)];
    }
    for (int idx = tid; idx < Br * H1S; idx += NTHR) sm[OFF_H1 + idx] = 0.0f;
    for (int idx = tid; idx < Br * H2S; idx += NTHR) sm[OFF_H2 + idx] = 0.0f;
    for (int i = tid; i < Br * 64; i += NTHR) {
        int r = i >> 6, f = i & 63;
        sm[OFF_XS + r * XSS + f] = x[((size_t)(g * Br + r) * Tlen) * 64 + f];
    }

    const int kcA = tid >> 6, rgA = (tid >> 3) & 7, ctA = tid & 7, rA0 = rgA * 2;
    const int kcB = tid >> 5, rgB = (tid >> 2) & 7, ctB = tid & 3, rB0 = rgB * 2;

    ull bzA[2], brA[2], bxA[2], bhA[2];
    if (kcA == 0) {
        #pragma unroll
        for (int p = 0; p < 2; p++) {
            int u0 = (c << 5) + ctA * 4 + p * 2, u1 = u0 + 1;
            bzA[p] = pk2(b1[u0] + b1[768 + u0],        b1[u1] + b1[768 + u1]);
            brA[p] = pk2(b1[256 + u0] + b1[1024 + u0], b1[256 + u1] + b1[1024 + u1]);
            bxA[p] = pk2(b1[512 + u0],                 b1[512 + u1]);
            bhA[p] = pk2(b1[1280 + u0],                b1[1280 + u1]);
        }
    }
    ull bzB[2], brB[2], bxB[2], bhB[2];
    if (kcB == 0) {
        #pragma unroll
        for (int p = 0; p < 2; p++) {
            int u0 = (c << 4) + ctB * 4 + p * 2, u1 = u0 + 1;
            bzB[p] = pk2(b2[u0] + b2[384 + u0],        b2[u1] + b2[384 + u1]);
            brB[p] = pk2(b2[128 + u0] + b2[512 + u0],  b2[128 + u1] + b2[512 + u1]);
            bxB[p] = pk2(b2[256 + u0],                 b2[256 + u1]);
            bhB[p] = pk2(b2[640 + u0],                 b2[640 + u1]);
        }
    }

    const uint32_t h1la = smem_base + (uint32_t)(OFF_H1 + rA0 * H1S + (c << 5) + ctA * 4) * 4u;
    const uint32_t h2la = smem_base + (uint32_t)(OFF_H2 + rB0 * H2S + (c << 4) + ctB * 4) * 4u;
    const ulonglong2* K1p = (const ulonglong2*)(sm + OFF_K1);
    const ulonglong2* R1p = (const ulonglong2*)(sm + OFF_R1);
    const ulonglong2* K2p = (const ulonglong2*)(sm + OFF_K2);
    const ulonglong2* R2p = (const ulonglong2*)(sm + OFF_R2);
    ull* scU = (ull*)(sm + OFF_SC);

    __syncthreads();
    cl_sync();   // mbarrier inits + weights visible cluster-wide

    for (int t = 0; t < Tlen; t++) {
        const uint32_t par = (uint32_t)(t & 1);
        float4 xr[4];
        if (kcA == 1 && t + 1 < Tlen) {     // x(t+1) -> regs
            #pragma unroll
            for (int j = 0; j < 4; j++) {
                int i = (tid - 64) * 4 + j, r = i >> 4, f4 = i & 15;
                xr[j] = *(const float4*)(x + ((size_t)(g * Br + r) * Tlen + t + 1) * 64 + f4 * 4);
            }
        }

        // ---- GRU1 projections (read x(t), h1(t-1)) ----
        ull az[2][2], ar[2][2], ax[2][2], ah[2][2];
        #pragma unroll
        for (int rr = 0; rr < 2; rr++)
            #pragma unroll
            for (int p = 0; p < 2; p++) {
                az[rr][p] = (kcA == 0) ? bzA[p] : 0ull;
                ar[rr][p] = (kcA == 0) ? brA[p] : 0ull;
                ax[rr][p] = (kcA == 0) ? bxA[p] : 0ull;
                ah[rr][p] = (kcA == 0) ? bhA[p] : 0ull;
            }
        const float* h0 = sm + OFF_H1 + rA0 * H1S;
        const float* h1r = h0 + H1S;
        if (kcA == 0) {
            const float* x0 = sm + OFF_XS + rA0 * XSS;
            const float* x1 = x0 + XSS;
            #pragma unroll 4
            for (int k = 0; k < 64; k++) {
                ull v0 = pk2(x0[k], x0[k]), v1 = pk2(x1[k], x1[k]);
                ulonglong2 wz = K1p[k * 24 + ctA], wr = K1p[k * 24 + 8 + ctA], wh = K1p[k * 24 + 16 + ctA];
                f2(az[0][0], v0, wz.x); f2(az[0][1], v0, wz.y);
                f2(az[1][0], v1, wz.x); f2(az[1][1], v1, wz.y);
                f2(ar[0][0], v0, wr.x); f2(ar[0][1], v0, wr.y);
                f2(ar[1][0], v1, wr.x); f2(ar[1][1], v1, wr.y);
                f2(ax[0][0], v0, wh.x); f2(ax[0][1], v0, wh.y);
                f2(ax[1][0], v1, wh.x); f2(ax[1][1], v1, wh.y);
            }
        }
        {
            const int kb = kcA ? 96 : 0, ke = kcA ? 256 : 96;
            #pragma unroll 4
            for (int k = kb; k < ke; k++) {
                ull v0 = pk2(h0[k], h0[k]), v1 = pk2(h1r[k], h1r[k]);
                ulonglong2 wz = R1p[k * 24 + ctA], wr = R1p[k * 24 + 8 + ctA], wh = R1p[k * 24 + 16 + ctA];
                f2(az[0][0], v0, wz.x); f2(az[0][1], v0, wz.y);
                f2(az[1][0], v1, wz.x); f2(az[1][1], v1, wz.y);
                f2(ar[0][0], v0, wr.x); f2(ar[0][1], v0, wr.y);
                f2(ar[1][0], v1, wr.x); f2(ar[1][1], v1, wr.y);
                f2(ah[0][0], v0, wh.x); f2(ah[0][1], v0, wh.y);
                f2(ah[1][0], v1, wh.x); f2(ah[1][1], v1, wh.y);
            }
        }

        // ---- GRU2 recurrent proj (read h2(t-1)) ----
        if (t > 0) mb_wait(mbRDY2, (uint32_t)((t - 1) & 1));
        ull bz[2][2], br_[2][2], bx[2][2], bh[2][2];
        #pragma unroll
        for (int rr = 0; rr < 2; rr++)
            #pragma unroll
            for (int p = 0; p < 2; p++) {
                bz[rr][p] = (kcB == 0) ? bzB[p] : 0ull;
                br_[rr][p] = (kcB == 0) ? brB[p] : 0ull;
                bx[rr][p] = (kcB == 0) ? bxB[p] : 0ull;
                bh[rr][p] = (kcB == 0) ? bhB[p] : 0ull;
            }
        {
            const float* g0 = sm + OFF_H2 + rB0 * H2S;
            const float* g1 = g0 + H2S;
            const int kb = kcB * 32;
            #pragma unroll 4
            for (int kk = 0; kk < 32; kk++) {
                int k = kb + kk;
                ull v0 = pk2(g0[k], g0[k]), v1 = pk2(g1[k], g1[k]);
                ulonglong2 wz = R2p[k * 12 + ctB], wr = R2p[k * 12 + 4 + ctB], wh = R2p[k * 12 + 8 + ctB];
                f2(bz[0][0], v0, wz.x); f2(bz[0][1], v0, wz.y);
                f2(bz[1][0], v1, wz.x); f2(bz[1][1], v1, wz.y);
                f2(br_[0][0], v0, wr.x); f2(br_[0][1], v0, wr.y);
                f2(br_[1][0], v1, wr.x); f2(br_[1][1], v1, wr.y);
                f2(bh[0][0], v0, wh.x); f2(bh[0][1], v0, wh.y);
                f2(bh[1][0], v1, wh.x); f2(bh[1][1], v1, wh.y);
            }
        }
        __syncthreads();                       // S1: all local reads of h1(t-1), h2(t-1), x(t) done
        if (tid < 8) mb_arrive_rel(mbFREE, (uint32_t)tid);

        if (kcA == 1) {                        // GRU1 partials + x(t+1) STS
            #pragma unroll
            for (int rr = 0; rr < 2; rr++) {
                int r = rA0 + rr;
                #pragma unroll
                for (int p = 0; p < 2; p++) {
                    scU[r * 50 +      ctA * 2 + p] = az[rr][p];
                    scU[r * 50 + 16 + ctA * 2 + p] = ar[rr][p];
                    scU[r * 50 + 32 + ctA * 2 + p] = ah[rr][p];
                }
            }
            if (t + 1 < Tlen) {
                #pragma unroll
                for (int j = 0; j < 4; j++) {
                    int i = (tid - 64) * 4 + j, r = i >> 4, f4 = i & 15;
                    *(float4*)(sm + OFF_XS + r * XSS + f4 * 4) = xr[j];
                }
            }
        }
        __syncthreads();                       // S2
        if (kcA == 0) {                        // reduce + gates + publish h1(t)
            float hn1[2][4];
            #pragma unroll
            for (int rr = 0; rr < 2; rr++) {
                int r = rA0 + rr;
                #pragma unroll
                for (int p = 0; p < 2; p++) {
                    a2(az[rr][p], scU[r * 50 +      ctA * 2 + p]);
                    a2(ar[rr][p], scU[r * 50 + 16 + ctA * 2 + p]);
                    a2(ah[rr][p], scU[r * 50 + 32 + ctA * 2 + p]);
                    float2 vz = upk(az[rr][p]), vr = upk(ar[rr][p]);
                    float2 vx = upk(ax[rr][p]), vh = upk(ah[rr][p]);
                    int col = (c << 5) + ctA * 4 + p * 2;
                    const float* hr = (rr == 0) ? h0 : h1r;
                    float z0 = sigf(vz.x), r0 = sigf(vr.x);
                    float hh0 = tanh_fast(vx.x + r0 * vh.x);
                    float z1 = sigf(vz.y), r1g = sigf(vr.y);
                    float hh1 = tanh_fast(vx.y + r1g * vh.y);
                    hn1[rr][p * 2]     = z0 * hr[col]     + (1.0f - z0) * hh0;
                    hn1[rr][p * 2 + 1] = z1 * hr[col + 1] + (1.0f - z1) * hh1;
                }
            }
            mb_wait(mbFREE, par);              // WAR: all copies free
            ull q00 = pk2(hn1[0][0], hn1[0][1]), q01 = pk2(hn1[0][2], hn1[0][3]);
            ull q10 = pk2(hn1[1][0], hn1[1][1]), q11 = pk2(hn1[1][2], hn1[1][3]);
            #pragma unroll
            for (int rk = 0; rk < CL; rk++) {
                uint32_t p0 = mapa_u32(h1la, (uint32_t)rk);
                st_rem64(p0, q00); st_rem64(p0 + 8, q01);
                uint32_t p1 = mapa_u32(h1la + H1S * 4, (uint32_t)rk);
                st_rem64(p1, q10); st_rem64(p1 + 8, q11);
            }
            asm volatile("bar.sync 1, 64;" ::: "memory");
            if (tid < 8) mb_arrive_rel(mbRDY1, (uint32_t)tid);
        }
        mb_wait(mbRDY1, par);                  // h1(t) visible locally

        // ---- GRU2 input proj (read h1(t)) ----
        {
            const float* g0 = sm + OFF_H1 + rB0 * H1S;
            const float* g1 = g0 + H1S;
            const int kb = kcB * 64;
            #pragma unroll 4
            for (int kk = 0; kk < 64; kk++) {
                int k = kb + kk;
                ull v0 = pk2(g0[k], g0[k]), v1 = pk2(g1[k], g1[k]);
                ulonglong2 wz = K2p[k * 12 + ctB], wr = K2p[k * 12 + 4 + ctB], wh = K2p[k * 12 + 8 + ctB];
                f2(bz[0][0], v0, wz.x); f2(bz[0][1], v0, wz.y);
                f2(bz[1][0], v1, wz.x); f2(bz[1][1], v1, wz.y);
                f2(br_[0][0], v0, wr.x); f2(br_[0][1], v0, wr.y);
                f2(br_[1][0], v1, wr.x); f2(br_[1][1], v1, wr.y);
                f2(bx[0][0], v0, wh.x); f2(bx[0][1], v0, wh.y);
                f2(bx[1][0], v1, wh.x); f2(bx[1][1], v1, wh.y);
            }
        }
        __syncthreads();                       // S3: GRU1 scratch reads done
        if (kcB > 0) {                         // phase 1: z, r
            int m = kcB - 1;
            #pragma unroll
            for (int rr = 0; rr < 2; rr++) {
                int r = rB0 + rr;
                #pragma unroll
                for (int p = 0; p < 2; p++) {
                    scU[m * 272 + r * 17 +     ctB * 2 + p] = bz[rr][p];
                    scU[m * 272 + r * 17 + 8 + ctB * 2 + p] = br_[rr][p];
                }
            }
        }
        __syncthreads();                       // S4
        if (kcB == 0) {
            #pragma unroll
            for (int m = 0; m < 3; m++)
                #pragma unroll
                for (int rr = 0; rr < 2; rr++) {
                    int r = rB0 + rr;
                    #pragma unroll
                    for (int p = 0; p < 2; p++) {
                        a2(bz[rr][p],  scU[m * 272 + r * 17 +     ctB * 2 + p]);
                        a2(br_[rr][p], scU[m * 272 + r * 17 + 8 + ctB * 2 + p]);
                    }
                }
        }
        __syncthreads();                       // S5
        if (kcB > 0) {                         // phase 2: hx, hh
            int m = kcB - 1;
            #pragma unroll
            for (int rr = 0; rr < 2; rr++) {
                int r = rB0 + rr;
                #pragma unroll
                for (int p = 0; p < 2; p++) {
                    scU[m * 272 + r * 17 +     ctB * 2 + p] = bx[rr][p];
                    scU[m * 272 + r * 17 + 8 + ctB * 2 + p] = bh[rr][p];
                }
            }
        }
        __syncthreads();                       // S6
        if (kcB == 0) {                        // reduce + gates + publish h2(t)
            float hn2[2][4];
            #pragma unroll
            for (int rr = 0; rr < 2; rr++) {
                int r = rB0 + rr;
                #pragma unroll
                for (int p = 0; p < 2; p++) {
                    #pragma unroll
                    for (int m = 0; m < 3; m++) {
                        a2(bx[rr][p], scU[m * 272 + r * 17 +     ctB * 2 + p]);
                        a2(bh[rr][p], scU[m * 272 + r * 17 + 8 + ctB * 2 + p]);
                    }
                    float2 vz = upk(bz[rr][p]), vr = upk(br_[rr][p]);
                    float2 vx = upk(bx[rr][p]), vh = upk(bh[rr][p]);
                    int col = (c << 4) + ctB * 4 + p * 2;
                    float hp0 = sm[OFF_H2 + r * H2S + col];
                    float hp1 = sm[OFF_H2 + r * H2S + col + 1];
                    float z0 = sigf(vz.x), r0 = sigf(vr.x);
                    float hh0 = tanh_fast(vx.x + r0 * vh.x);
                    float z1 = sigf(vz.y), r1g = sigf(vr.y);
                    float hh1 = tanh_fast(vx.y + r1g * vh.y);
                    hn2[rr][p * 2]     = z0 * hp0 + (1.0f - z0) * hh0;
                    hn2[rr][p * 2 + 1] = z1 * hp1 + (1.0f - z1) * hh1;
                }
            }
            mb_wait(mbFREE, par);              // already complete; acquire only
            ull q00 = pk2(hn2[0][0], hn2[0][1]), q01 = pk2(hn2[0][2], hn2[0][3]);
            ull q10 = pk2(hn2[1][0], hn2[1][1]), q11 = pk2(hn2[1][2], hn2[1][3]);
            #pragma unroll
            for (int rk = 0; rk < CL; rk++) {
                uint32_t p0 = mapa_u32(h2la, (uint32_t)rk);
                st_rem64(p0, q00); st_rem64(p0 + 8, q01);
                uint32_t p1 = mapa_u32(h2la + H2S * 4, (uint32_t)rk);
                st_rem64(p1, q10); st_rem64(p1 + 8, q11);
            }
            __syncwarp();
            if (tid < 8) mb_arrive_rel(mbRDY2, (uint32_t)tid);
        }
    }
    mb_wait(mbRDY2, (uint32_t)((Tlen - 1) & 1));   // final h2 delivered; safe to exit

    if (c == 0) {
        float* sD3 = sm + OFF_SC;
        float* sD4 = sm + OFF_SC + Br * 64;
        __syncthreads();
        for (int idx = tid; idx < Br * 64; idx += NTHR) {
            int r = idx >> 6, o = idx & 63;
            float a = b3[o];
            #pragma unroll 8
            for (int k = 0; k < 128; k++) a += sm[OFF_H2 + r * H2S + k] * w3[k * 64 + o];
            sD3[idx] = a;
        }
        __syncthreads();
        for (int idx = tid; idx < Br * 32; idx += NTHR) {
            int r = idx >> 5, o = idx & 31;
            float a = b4[o];
            #pragma unroll 8
            for (int k = 0; k < 64; k++) a += sD3[r * 64 + k] * w4[k * 32 + o];
            sD4[idx] = a;
        }
        __syncthreads();
        for (int idx = tid; idx < Br * OUTW; idx += NTHR) {
            int r = idx / OUTW, o = idx % OUTW;
            float a = b5[o];
            #pragma unroll 8
            for (int k = 0; k < 32; k++) a += sD4[r * 32 + k] * w5[k * OUTW + o];
            out[(g * Br + r) * OUTW + o] = a;
        }
    }
}

extern "C" void kernel_launch(void* const* d_in, const int* in_sizes, int n_in,
                              void* d_out, int out_size) {
    (void)in_sizes; (void)n_in; (void)out_size;
    const float* x  = (const float*)d_in[0];
    const float* k1 = (const float*)d_in[1];
    const float* r1 = (const float*)d_in[2];
    const float* b1 = (const float*)d_in[3];
    const float* k2 = (const float*)d_in[4];
    const float* r2 = (const float*)d_in[5];
    const float* b2 = (const float*)d_in[6];
    const float* w3 = (const float*)d_in[7];
    const float* b3 = (const float*)d_in[8];
    const float* w4 = (const float*)d_in[9];
    const float* b4 = (const float*)d_in[10];
    const float* w5 = (const float*)d_in[11];
    const float* b5 = (const float*)d_in[12];
    float* out = (float*)d_out;

    cudaFuncSetAttribute(gru_stack_kernel,
                         cudaFuncAttributeMaxDynamicSharedMemorySize, (int)SMEM_BYTES);
    gru_stack_kernel<<<128, NTHR, SMEM_BYTES>>>(
        x, k1, r1, b1, k2, r2, b2, w3, b3, w4, b4, w5, b5, out);
}